// round 2
// baseline (speedup 1.0000x reference)
#include <cuda_runtime.h>
#include <cstddef>

// E=512, H=512, S=T=2048, NT=2
// Directions d: 0=src_fwd, 1=src_bwd, 2=tgt_fwd, 3=tgt_bwd

// ---------------- static device scratch ----------------
__device__ float  g_gx[4ll * 2048 * 1536];     // precomputed input gates per direction
__device__ float  g_src_out[2048ll * 1024];    // src BiGRU output [S, 2H]
__device__ float  g_tgt_out[2048ll * 1024];    // tgt BiGRU output [T, 2H]
__device__ float  g_align[2ll * 2048 * 2048];  // z=0 cross logits, z=1 self logits
__device__ int    g_flags[128];                // GRU step barrier slots (32 per direction)
__device__ float  g_y[3][4096];                // y1=tgt@W1^T, y2=src@W2^T, y3=tgt@W3^T [2048,2]
__device__ float  g_ctxE[2][4096];             // softmax-weighted y2 / y3 [2048,2]
__device__ float  g_emit[4096];                // emit [2048,2]
__device__ double g_matsA[2048 * 4];           // CRF log-semiring matrices
__device__ double g_matsB[2048 * 4];

struct P4 { const float* p[4]; };

// ---------------- helpers ----------------
__device__ __forceinline__ int ldacq(const int* p) {
    int v;
    asm volatile("ld.acquire.gpu.b32 %0, [%1];" : "=r"(v) : "l"(p) : "memory");
    return v;
}
__device__ __forceinline__ void strel(int* p, int v) {
    asm volatile("st.release.gpu.b32 [%0], %1;" :: "l"(p), "r"(v) : "memory");
}
__device__ __forceinline__ double lse2d(double a, double b) {
    double m = fmax(a, b);
    double d = fmin(a, b) - m;   // <= 0
    return m + (double)log1pf(expf((float)d));
}

// ---------------- init: zero barrier slots ----------------
__global__ void init_kernel() {
    if (threadIdx.x < 128) g_flags[threadIdx.x] = 0;
}

// ---------------- generic NT GEMM: C[M,N] = scale*(A[M,K] @ B[N,K]^T) + bias, opt diag mask ----
// 128x128 tile, BK=8, 256 threads, 8x8 per thread, double-buffered smem.
__device__ __forceinline__ void gemm_nt(
    const float* __restrict__ A, const float* __restrict__ B, float* __restrict__ C,
    int N, int K, const float* __restrict__ bias, float scale, bool diagmask)
{
    __shared__ __align__(16) float As[2][8][128];
    __shared__ __align__(16) float Bs[2][8][128];
    const int tid = threadIdx.x;
    const int lr = tid >> 1;            // 0..127: row within tile
    const int lk = (tid & 1) << 2;      // 0 or 4
    const float* Ag = A + (size_t)(blockIdx.y * 128 + lr) * K + lk;
    const float* Bg = B + (size_t)(blockIdx.x * 128 + lr) * K + lk;

    float4 a4 = *(const float4*)Ag;
    float4 b4 = *(const float4*)Bg;
    int buf = 0;
    As[0][lk + 0][lr] = a4.x; As[0][lk + 1][lr] = a4.y; As[0][lk + 2][lr] = a4.z; As[0][lk + 3][lr] = a4.w;
    Bs[0][lk + 0][lr] = b4.x; Bs[0][lk + 1][lr] = b4.y; Bs[0][lk + 2][lr] = b4.z; Bs[0][lk + 3][lr] = b4.w;
    __syncthreads();

    float acc[8][8];
#pragma unroll
    for (int i = 0; i < 8; i++)
#pragma unroll
        for (int j = 0; j < 8; j++) acc[i][j] = 0.0f;

    const int ty = tid >> 4, tx = tid & 15;
    const int ktiles = K >> 3;
    for (int kt = 1; kt <= ktiles; ++kt) {
        float4 na, nb;
        if (kt < ktiles) {
            na = *(const float4*)(Ag + kt * 8);
            nb = *(const float4*)(Bg + kt * 8);
        }
#pragma unroll
        for (int k = 0; k < 8; ++k) {
            float ra[8], rb[8];
            *(float4*)&ra[0] = *(const float4*)&As[buf][k][ty * 8];
            *(float4*)&ra[4] = *(const float4*)&As[buf][k][ty * 8 + 4];
            *(float4*)&rb[0] = *(const float4*)&Bs[buf][k][tx * 8];
            *(float4*)&rb[4] = *(const float4*)&Bs[buf][k][tx * 8 + 4];
#pragma unroll
            for (int i = 0; i < 8; i++)
#pragma unroll
                for (int j = 0; j < 8; j++) acc[i][j] = fmaf(ra[i], rb[j], acc[i][j]);
        }
        if (kt < ktiles) {
            buf ^= 1;
            As[buf][lk + 0][lr] = na.x; As[buf][lk + 1][lr] = na.y; As[buf][lk + 2][lr] = na.z; As[buf][lk + 3][lr] = na.w;
            Bs[buf][lk + 0][lr] = nb.x; Bs[buf][lk + 1][lr] = nb.y; Bs[buf][lk + 2][lr] = nb.z; Bs[buf][lk + 3][lr] = nb.w;
            __syncthreads();
        }
    }

    const int gm0 = blockIdx.y * 128 + ty * 8;
    const int gn0 = blockIdx.x * 128 + tx * 8;
    float bv[8];
#pragma unroll
    for (int j = 0; j < 8; j++) bv[j] = bias ? bias[gn0 + j] : 0.0f;
#pragma unroll
    for (int i = 0; i < 8; i++) {
        int gm = gm0 + i;
        float o[8];
#pragma unroll
        for (int j = 0; j < 8; j++) {
            o[j] = fmaf(acc[i][j], scale, bv[j]);
            if (diagmask && gm == gn0 + j) o[j] = -1e30f;
        }
        float4* cp = (float4*)(C + (size_t)gm * N + gn0);
        cp[0] = make_float4(o[0], o[1], o[2], o[3]);
        cp[1] = make_float4(o[4], o[5], o[6], o[7]);
    }
}

__global__ __launch_bounds__(256) void gx_gemm_kernel(P4 xs, P4 wih, P4 bih) {
    int z = blockIdx.z;
    gemm_nt(xs.p[z], wih.p[z], g_gx + (size_t)z * 2048 * 1536, 1536, 512, bih.p[z], 1.0f, false);
}

__global__ __launch_bounds__(256) void logits_gemm_kernel() {
    int z = blockIdx.z;
    // temp = sqrt(1/(2H)) = 1/32 -> scale 32
    gemm_nt(g_tgt_out, z ? g_tgt_out : g_src_out,
            g_align + (size_t)z * 2048 * 2048, 2048, 1024, nullptr, 32.0f, z == 1);
}

// ---------------- GRU recurrence: 4 directions x 32 CTAs, weight-stationary ----------------
__global__ __launch_bounds__(512, 1) void gru_kernel(P4 whh, P4 bhh) {
    const int d = blockIdx.x >> 5;
    const int b = blockIdx.x & 31;
    const int tid = threadIdx.x;
    const int w = tid >> 5, lane = tid & 31;
    const int j = b * 16 + w;           // hidden index owned by this warp
    const bool rev = (d & 1) != 0;
    float* out = (d < 2) ? g_src_out : g_tgt_out;
    const int col = rev ? 512 : 0;
    const float* gx = g_gx + (size_t)d * 2048 * 1536;
    const float* Whh = whh.p[d];

    float wr[16], wz[16], wn[16];
#pragma unroll
    for (int i = 0; i < 16; i++) {
        int k = lane + 32 * i;
        wr[i] = Whh[(size_t)j * 512 + k];
        wz[i] = Whh[(size_t)(512 + j) * 512 + k];
        wn[i] = Whh[(size_t)(1024 + j) * 512 + k];
    }
    const float* bh = bhh.p[d];
    const float b_r = bh[j], b_z = bh[512 + j], b_n = bh[1024 + j];

    __shared__ float hsm[512];
    hsm[tid] = 0.0f;
    __syncthreads();

    int* flg = g_flags + d * 32;

    // prefetch gx for first step
    float gxr = 0.f, gxz = 0.f, gxn = 0.f;
    if (lane == 0) {
        const float* g0 = gx + (size_t)(rev ? 2047 : 0) * 1536;
        gxr = g0[j]; gxz = g0[512 + j]; gxn = g0[1024 + j];
    }

    for (int s = 0; s < 2048; ++s) {
        const int idx = rev ? (2047 - s) : s;

        float ar = 0.f, az = 0.f, an = 0.f;
#pragma unroll
        for (int i = 0; i < 16; i++) {
            float hv = hsm[lane + 32 * i];
            ar = fmaf(wr[i], hv, ar);
            az = fmaf(wz[i], hv, az);
            an = fmaf(wn[i], hv, an);
        }
#pragma unroll
        for (int o = 16; o > 0; o >>= 1) {
            ar += __shfl_down_sync(0xffffffffu, ar, o);
            az += __shfl_down_sync(0xffffffffu, az, o);
            an += __shfl_down_sync(0xffffffffu, an, o);
        }
        if (lane == 0) {
            float r = 1.0f / (1.0f + expf(-(gxr + ar + b_r)));
            float z = 1.0f / (1.0f + expf(-(gxz + az + b_z)));
            float n = tanhf(gxn + r * (an + b_n));
            float hnew = (1.0f - z) * n + z * hsm[j];
            out[(size_t)idx * 1024 + col + j] = hnew;
            // prefetch gx for next step (completes during the barrier wait)
            int sn = s + 1;
            if (sn < 2048) {
                const float* gn_ = gx + (size_t)(rev ? 2047 - sn : sn) * 1536;
                gxr = gn_[j]; gxz = gn_[512 + j]; gxn = gn_[1024 + j];
            }
        }
        __syncthreads();
        if (tid == 0) {
            __threadfence();
            strel(flg + b, s + 1);
        }
        if (tid < 32) {
            while (ldacq(flg + tid) <= s) { }
        }
        __syncthreads();
        hsm[tid] = out[(size_t)idx * 1024 + col + tid];
        __syncthreads();
    }
}

// ---------------- y projections: y[z][t,c] = A[t,:] . W_emit[c, z*1024 : z*1024+1024] ----------
__global__ __launch_bounds__(128) void y_kernel(const float* __restrict__ W_emit) {
    const int t = blockIdx.x, z = blockIdx.y;  // z: 0->y1(tgt), 1->y2(src), 2->y3(tgt)
    const float* A = (z == 1) ? g_src_out : g_tgt_out;
    const float* w0 = W_emit + z * 1024;
    const float* w1 = W_emit + 3072 + z * 1024;
    const float* a = A + (size_t)t * 1024;
    float s0 = 0.f, s1 = 0.f;
    for (int k = threadIdx.x; k < 1024; k += 128) {
        float av = a[k];
        s0 = fmaf(av, w0[k], s0);
        s1 = fmaf(av, w1[k], s1);
    }
#pragma unroll
    for (int o = 16; o > 0; o >>= 1) {
        s0 += __shfl_down_sync(0xffffffffu, s0, o);
        s1 += __shfl_down_sync(0xffffffffu, s1, o);
    }
    __shared__ float r0[4], r1[4];
    const int w = threadIdx.x >> 5, lane = threadIdx.x & 31;
    if (lane == 0) { r0[w] = s0; r1[w] = s1; }
    __syncthreads();
    if (threadIdx.x == 0) {
        g_y[z][t * 2 + 0] = r0[0] + r0[1] + r0[2] + r0[3];
        g_y[z][t * 2 + 1] = r1[0] + r1[1] + r1[2] + r1[3];
    }
}

// ---------------- fused softmax + weighted [.,2] reduction per row ----------------
__global__ __launch_bounds__(256) void softmax_kernel() {
    const int t = blockIdx.x, z = blockIdx.y;
    const float* L = g_align + (size_t)z * 2048 * 2048 + (size_t)t * 2048;
    const float* yv = g_y[z + 1];  // z=0 -> y2 (src values), z=1 -> y3 (tgt values)
    __shared__ float red[3][8];
    const int tid = threadIdx.x, w = tid >> 5, lane = tid & 31;

    float lv[8];
    float m = -1e30f;
#pragma unroll
    for (int i = 0; i < 8; i++) { lv[i] = L[tid + 256 * i]; m = fmaxf(m, lv[i]); }
#pragma unroll
    for (int o = 16; o > 0; o >>= 1) m = fmaxf(m, __shfl_xor_sync(0xffffffffu, m, o));
    if (lane == 0) red[0][w] = m;
    __syncthreads();
    m = fmaxf(fmaxf(fmaxf(red[0][0], red[0][1]), fmaxf(red[0][2], red[0][3])),
              fmaxf(fmaxf(red[0][4], red[0][5]), fmaxf(red[0][6], red[0][7])));
    __syncthreads();

    float Zs = 0.f, w0 = 0.f, w1 = 0.f;
#pragma unroll
    for (int i = 0; i < 8; i++) {
        int s = tid + 256 * i;
        float e = expf(lv[i] - m);
        Zs += e;
        w0 = fmaf(e, yv[s * 2 + 0], w0);
        w1 = fmaf(e, yv[s * 2 + 1], w1);
    }
#pragma unroll
    for (int o = 16; o > 0; o >>= 1) {
        Zs += __shfl_down_sync(0xffffffffu, Zs, o);
        w0 += __shfl_down_sync(0xffffffffu, w0, o);
        w1 += __shfl_down_sync(0xffffffffu, w1, o);
    }
    if (lane == 0) { red[0][w] = Zs; red[1][w] = w0; red[2][w] = w1; }
    __syncthreads();
    if (tid == 0) {
        float Z = 0.f, W0 = 0.f, W1 = 0.f;
#pragma unroll
        for (int q = 0; q < 8; q++) { Z += red[0][q]; W0 += red[1][q]; W1 += red[2][q]; }
        g_ctxE[z][t * 2 + 0] = W0 / Z;
        g_ctxE[z][t * 2 + 1] = W1 / Z;
    }
}

// ---------------- CRF: gold score + partition via parallel log-semiring scan ----------------
__global__ __launch_bounds__(1024) void crf_kernel(
    const int* __restrict__ labels, const float* __restrict__ b_emit,
    const float* __restrict__ t_start, const float* __restrict__ t_trans,
    const float* __restrict__ t_end, float* __restrict__ outp)
{
    const int tid = threadIdx.x;
    __shared__ double red[1024];
    __shared__ float tr[4];
    if (tid < 4) tr[tid] = t_trans[tid];
    __syncthreads();
    const float be0 = b_emit[0], be1 = b_emit[1];

    double acc = 0.0;
    for (int t = tid; t < 2048; t += 1024) {
        float e0 = g_y[0][t * 2 + 0] + g_ctxE[0][t * 2 + 0] + g_ctxE[1][t * 2 + 0] + be0;
        float e1 = g_y[0][t * 2 + 1] + g_ctxE[0][t * 2 + 1] + g_ctxE[1][t * 2 + 1] + be1;
        g_emit[t * 2 + 0] = e0;
        g_emit[t * 2 + 1] = e1;
        int lab = labels[t];
        acc += (double)(lab ? e1 : e0);
        if (t >= 1) {
            acc += (double)tr[lab * 2 + labels[t - 1]];
            // M_t[i][j] = trans[i][j] + emit[t][i], stored at index t-1
            double* M = g_matsA + (size_t)(t - 1) * 4;
            M[0] = (double)tr[0] + (double)e0;
            M[1] = (double)tr[1] + (double)e0;
            M[2] = (double)tr[2] + (double)e1;
            M[3] = (double)tr[3] + (double)e1;
        }
    }
    red[tid] = acc;
    __syncthreads();
    for (int o = 512; o > 0; o >>= 1) {
        if (tid < o) red[tid] += red[tid + o];
        __syncthreads();
    }

    // tree-reduce 2047 matrices: out[i] = arr[2i+1] (later) (x) arr[2i] (earlier)
    double* A = g_matsA;
    double* B = g_matsB;
    int n = 2047;
    while (n > 1) {
        int m = n >> 1;
        for (int i = tid; i < m; i += 1024) {
            const double* Lm = A + (size_t)(2 * i + 1) * 4;
            const double* Rm = A + (size_t)(2 * i) * 4;
            double o0 = lse2d(Lm[0] + Rm[0], Lm[1] + Rm[2]);
            double o1 = lse2d(Lm[0] + Rm[1], Lm[1] + Rm[3]);
            double o2 = lse2d(Lm[2] + Rm[0], Lm[3] + Rm[2]);
            double o3 = lse2d(Lm[2] + Rm[1], Lm[3] + Rm[3]);
            double* O = B + (size_t)i * 4;
            O[0] = o0; O[1] = o1; O[2] = o2; O[3] = o3;
        }
        if ((n & 1) && tid == 0) {
#pragma unroll
            for (int q = 0; q < 4; q++) B[(size_t)m * 4 + q] = A[(size_t)(n - 1) * 4 + q];
        }
        n = m + (n & 1);
        __syncthreads();
        double* tp = A; A = B; B = tp;
    }

    if (tid == 0) {
        double gold = red[0] + (double)t_start[labels[0]] + (double)t_end[labels[2047]];
        double a0 = (double)t_start[0] + (double)g_emit[0];
        double a1 = (double)t_start[1] + (double)g_emit[1];
        const double* Pm = A;
        double aT0 = lse2d(Pm[0] + a0, Pm[1] + a1);
        double aT1 = lse2d(Pm[2] + a0, Pm[3] + a1);
        double logZ = lse2d((double)t_end[0] + aT0, (double)t_end[1] + aT1);
        outp[0] = (float)(gold - logZ);
    }
}

// ---------------- launch ----------------
extern "C" void kernel_launch(void* const* d_in, const int* in_sizes, int n_in,
                              void* d_out, int out_size) {
    const float* source  = (const float*)d_in[0];
    const float* target  = (const float*)d_in[1];
    const int*   labels  = (const int*)d_in[2];
    P4 xs, wih, whh, bih, bhh;
    for (int d = 0; d < 4; d++) {
        int base = 3 + 4 * d;
        wih.p[d] = (const float*)d_in[base + 0];
        whh.p[d] = (const float*)d_in[base + 1];
        bih.p[d] = (const float*)d_in[base + 2];
        bhh.p[d] = (const float*)d_in[base + 3];
        xs.p[d]  = (d < 2) ? source : target;
    }
    const float* W_emit  = (const float*)d_in[19];
    const float* b_emit  = (const float*)d_in[20];
    const float* t_start = (const float*)d_in[21];
    const float* t_trans = (const float*)d_in[22];
    const float* t_end   = (const float*)d_in[23];
    float* outp = (float*)d_out;

    init_kernel<<<1, 128>>>();
    gx_gemm_kernel<<<dim3(12, 16, 4), 256>>>(xs, wih, bih);
    gru_kernel<<<128, 512>>>(whh, bhh);
    logits_gemm_kernel<<<dim3(16, 16, 2), 256>>>();
    y_kernel<<<dim3(2048, 3), 128>>>(W_emit);
    softmax_kernel<<<dim3(2048, 2), 256>>>();
    crf_kernel<<<1, 1024>>>(labels, b_emit, t_start, t_trans, t_end, outp);
}

// round 4
// speedup vs baseline: 2.0393x; 2.0393x over previous
#include <cuda_runtime.h>
#include <cstddef>

// E=512, H=512, S=T=2048, NT=2
// Directions d: 0=src_fwd, 1=src_bwd, 2=tgt_fwd, 3=tgt_bwd

// ---------------- static device scratch ----------------
__device__ float  g_gx[4ll * 2048 * 1536];     // input gates; r/z cols also serve as atomic accumulators
__device__ float  g_ghn[4ll * 2048 * 512];     // n-gate hidden partial sums (atomic accumulators)
__device__ float  g_src_out[2048ll * 1024];    // src BiGRU output [S, 2H]
__device__ float  g_tgt_out[2048ll * 1024];    // tgt BiGRU output [T, 2H]
__device__ float  g_align[2ll * 2048 * 2048];  // z=0 cross logits, z=1 self logits
__device__ int    g_cnt[4 * 2048];             // per (direction, step) arrival counters
__device__ float  g_y[3][4096];                // y1=tgt@W1^T, y2=src@W2^T, y3=tgt@W3^T [2048,2]
__device__ float  g_ctxE[2][4096];             // softmax-weighted y2 / y3 [2048,2]
__device__ float  g_emit[4096];                // emit [2048,2]
__device__ double g_matsA[2048 * 4];           // CRF log-semiring matrices
__device__ double g_matsB[2048 * 4];

struct P4 { const float* p[4]; };

// ---------------- helpers ----------------
__device__ __forceinline__ int ldacq(const int* p) {
    int v;
    asm volatile("ld.acquire.gpu.b32 %0, [%1];" : "=r"(v) : "l"(p) : "memory");
    return v;
}
__device__ __forceinline__ void red_release_add(int* p) {
    asm volatile("red.release.gpu.global.add.u32 [%0], 1;" :: "l"(p) : "memory");
}
__device__ __forceinline__ double lse2d(double a, double b) {
    double m = fmax(a, b);
    double d = fmin(a, b) - m;   // <= 0
    return m + (double)log1pf(expf((float)d));
}
__device__ __forceinline__ float fast_sigmoid(float x) {
    return 1.0f / (1.0f + __expf(-x));   // x << 0: expf->inf, 1/inf = 0 (safe)
}
__device__ __forceinline__ float fast_tanh(float x) {
    float t = __expf(-2.0f * fabsf(x));  // in (0,1], no overflow
    float m = (1.0f - t) / (1.0f + t);
    return copysignf(m, x);
}

// ---------------- init: zero n-partials + counters ----------------
__global__ __launch_bounds__(1024) void zero_kernel() {
    size_t i = (size_t)blockIdx.x * 1024 + threadIdx.x;
    g_ghn[i] = 0.0f;                     // grid sized exactly 4*2048*512/1024
    if (i < 4 * 2048) g_cnt[i] = 0;
}

// ---------------- generic NT GEMM: C[M,N] = scale*(A[M,K] @ B[N,K]^T) + bias, opt diag mask ----
// 128x128 tile, BK=8, 256 threads, 8x8 per thread, double-buffered smem.
__device__ __forceinline__ void gemm_nt(
    const float* __restrict__ A, const float* __restrict__ B, float* __restrict__ C,
    int N, int K, const float* __restrict__ bias, float scale, bool diagmask)
{
    __shared__ __align__(16) float As[2][8][128];
    __shared__ __align__(16) float Bs[2][8][128];
    const int tid = threadIdx.x;
    const int lr = tid >> 1;            // 0..127: row within tile
    const int lk = (tid & 1) << 2;      // 0 or 4
    const float* Ag = A + (size_t)(blockIdx.y * 128 + lr) * K + lk;
    const float* Bg = B + (size_t)(blockIdx.x * 128 + lr) * K + lk;

    float4 a4 = *(const float4*)Ag;
    float4 b4 = *(const float4*)Bg;
    int buf = 0;
    As[0][lk + 0][lr] = a4.x; As[0][lk + 1][lr] = a4.y; As[0][lk + 2][lr] = a4.z; As[0][lk + 3][lr] = a4.w;
    Bs[0][lk + 0][lr] = b4.x; Bs[0][lk + 1][lr] = b4.y; Bs[0][lk + 2][lr] = b4.z; Bs[0][lk + 3][lr] = b4.w;
    __syncthreads();

    float acc[8][8];
#pragma unroll
    for (int i = 0; i < 8; i++)
#pragma unroll
        for (int j = 0; j < 8; j++) acc[i][j] = 0.0f;

    const int ty = tid >> 4, tx = tid & 15;
    const int ktiles = K >> 3;
    for (int kt = 1; kt <= ktiles; ++kt) {
        float4 na, nb;
        if (kt < ktiles) {
            na = *(const float4*)(Ag + kt * 8);
            nb = *(const float4*)(Bg + kt * 8);
        }
#pragma unroll
        for (int k = 0; k < 8; ++k) {
            float ra[8], rb[8];
            *(float4*)&ra[0] = *(const float4*)&As[buf][k][ty * 8];
            *(float4*)&ra[4] = *(const float4*)&As[buf][k][ty * 8 + 4];
            *(float4*)&rb[0] = *(const float4*)&Bs[buf][k][tx * 8];
            *(float4*)&rb[4] = *(const float4*)&Bs[buf][k][tx * 8 + 4];
#pragma unroll
            for (int i = 0; i < 8; i++)
#pragma unroll
                for (int j = 0; j < 8; j++) acc[i][j] = fmaf(ra[i], rb[j], acc[i][j]);
        }
        if (kt < ktiles) {
            buf ^= 1;
            As[buf][lk + 0][lr] = na.x; As[buf][lk + 1][lr] = na.y; As[buf][lk + 2][lr] = na.z; As[buf][lk + 3][lr] = na.w;
            Bs[buf][lk + 0][lr] = nb.x; Bs[buf][lk + 1][lr] = nb.y; Bs[buf][lk + 2][lr] = nb.z; Bs[buf][lk + 3][lr] = nb.w;
            __syncthreads();
        }
    }

    const int gm0 = blockIdx.y * 128 + ty * 8;
    const int gn0 = blockIdx.x * 128 + tx * 8;
    float bv[8];
#pragma unroll
    for (int j = 0; j < 8; j++) bv[j] = bias ? bias[gn0 + j] : 0.0f;
#pragma unroll
    for (int i = 0; i < 8; i++) {
        int gm = gm0 + i;
        float o[8];
#pragma unroll
        for (int j = 0; j < 8; j++) {
            o[j] = fmaf(acc[i][j], scale, bv[j]);
            if (diagmask && gm == gn0 + j) o[j] = -1e30f;
        }
        float4* cp = (float4*)(C + (size_t)gm * N + gn0);
        cp[0] = make_float4(o[0], o[1], o[2], o[3]);
        cp[1] = make_float4(o[4], o[5], o[6], o[7]);
    }
}

__global__ __launch_bounds__(256) void gx_gemm_kernel(P4 xs, P4 wih, P4 bih) {
    int z = blockIdx.z;
    gemm_nt(xs.p[z], wih.p[z], g_gx + (size_t)z * 2048 * 1536, 1536, 512, bih.p[z], 1.0f, false);
}

__global__ __launch_bounds__(256) void logits_gemm_kernel() {
    int z = blockIdx.z;
    // temp = sqrt(1/(2H)) = 1/32 -> scale 32
    gemm_nt(g_tgt_out, z ? g_tgt_out : g_src_out,
            g_align + (size_t)z * 2048 * 2048, 2048, 1024, nullptr, 32.0f, z == 1);
}

// ---------------- GRU recurrence: stationary-h outer-product formulation ----------------
// Direction d has 32 CTAs; CTA b permanently owns h[16b .. 16b+16).
// Per step: thread t (0..511) adds its CTA's h-slice contribution to gate columns t
// (r into g_gx[idx][t], z into g_gx[idx][512+t], n into g_ghn[idx][t]) via REDG,
// then a per-step counter barrier; 16 lanes finish activations for the owned slice.
__global__ __launch_bounds__(512, 1) void gru_kernel(P4 whh, P4 bhh) {
    const int d = blockIdx.x >> 5;
    const int b = blockIdx.x & 31;
    const int tid = threadIdx.x;
    const bool rev = (d & 1) != 0;
    float* out = (d < 2) ? g_src_out : g_tgt_out;
    const int col = rev ? 512 : 0;
    const int J0 = b * 16;

    // Weight-stationary: thread t holds Whh[t][J0..J0+16), Whh[512+t][...], Whh[1024+t][...]
    const float* W = whh.p[d];
    float wr[16], wz[16], wn[16];
#pragma unroll
    for (int q = 0; q < 4; q++) {
        float4 v;
        v = *(const float4*)(W + (size_t)tid * 512 + J0 + 4 * q);
        wr[4 * q + 0] = v.x; wr[4 * q + 1] = v.y; wr[4 * q + 2] = v.z; wr[4 * q + 3] = v.w;
        v = *(const float4*)(W + (size_t)(512 + tid) * 512 + J0 + 4 * q);
        wz[4 * q + 0] = v.x; wz[4 * q + 1] = v.y; wz[4 * q + 2] = v.z; wz[4 * q + 3] = v.w;
        v = *(const float4*)(W + (size_t)(1024 + tid) * 512 + J0 + 4 * q);
        wn[4 * q + 0] = v.x; wn[4 * q + 1] = v.y; wn[4 * q + 2] = v.z; wn[4 * q + 3] = v.w;
    }

    // Activation-lane constants (lanes 0..15 own h index j = J0 + tid)
    float b_r = 0.f, b_z = 0.f, b_n = 0.f;
    if (tid < 16) {
        const float* bh = bhh.p[d];
        b_r = bh[J0 + tid]; b_z = bh[512 + J0 + tid]; b_n = bh[1024 + J0 + tid];
    }

    __shared__ float hsm[16];
    if (tid < 16) hsm[tid] = 0.0f;
    __syncthreads();

    int* cnt = g_cnt + d * 2048;
    float* gx = g_gx + (size_t)d * 2048 * 1536;
    float* ghn = g_ghn + (size_t)d * 2048 * 512;

    float h0 = 0.f;  // activation lane's current h value (kept in register)

    for (int s = 0; s < 2048; ++s) {
        const int idx = rev ? (2047 - s) : s;
        float* rowRZ = gx + (size_t)idx * 1536;
        float* rowN  = ghn + (size_t)idx * 512;

        // outer-product partials: this CTA's 16 h values into gate columns `tid`
        float ar = 0.f, az = 0.f, an = 0.f;
#pragma unroll
        for (int i = 0; i < 16; i++) {
            float hv = hsm[i];
            ar = fmaf(wr[i], hv, ar);
            az = fmaf(wz[i], hv, az);
            an = fmaf(wn[i], hv, an);
        }
        atomicAdd(rowRZ + tid, ar);
        atomicAdd(rowRZ + 512 + tid, az);
        atomicAdd(rowN + tid, an);

        __syncthreads();                 // all REDs issued by this CTA
        if (tid == 0) {
            red_release_add(cnt + s);    // release: our REDs visible before count
            while (ldacq(cnt + s) < 32) { }
        }
        __syncthreads();                 // whole direction's sums are complete

        if (tid < 16) {
            const int j = J0 + tid;
            float sr  = __ldcg(rowRZ + j);
            float sz  = __ldcg(rowRZ + 512 + j);
            float gxn = __ldcg(rowRZ + 1024 + j);
            float anj = __ldcg(rowN + j);
            float r = fast_sigmoid(sr + b_r);
            float z = fast_sigmoid(sz + b_z);
            float n = fast_tanh(fmaf(r, anj + b_n, gxn));
            h0 = (1.0f - z) * n + z * h0;
            hsm[tid] = h0;
            out[(size_t)idx * 1024 + col + j] = h0;
        }
        __syncthreads();                 // new h slice visible for next step's FMAs
    }
}

// ---------------- y projections: y[z][t,c] = A[t,:] . W_emit[c, z*1024 : z*1024+1024] ----------
__global__ __launch_bounds__(128) void y_kernel(const float* __restrict__ W_emit) {
    const int t = blockIdx.x, z = blockIdx.y;  // z: 0->y1(tgt), 1->y2(src), 2->y3(tgt)
    const float* A = (z == 1) ? g_src_out : g_tgt_out;
    const float* w0 = W_emit + z * 1024;
    const float* w1 = W_emit + 3072 + z * 1024;
    const float* a = A + (size_t)t * 1024;
    float s0 = 0.f, s1 = 0.f;
    for (int k = threadIdx.x; k < 1024; k += 128) {
        float av = a[k];
        s0 = fmaf(av, w0[k], s0);
        s1 = fmaf(av, w1[k], s1);
    }
#pragma unroll
    for (int o = 16; o > 0; o >>= 1) {
        s0 += __shfl_down_sync(0xffffffffu, s0, o);
        s1 += __shfl_down_sync(0xffffffffu, s1, o);
    }
    __shared__ float r0[4], r1[4];
    const int w = threadIdx.x >> 5, lane = threadIdx.x & 31;
    if (lane == 0) { r0[w] = s0; r1[w] = s1; }
    __syncthreads();
    if (threadIdx.x == 0) {
        g_y[z][t * 2 + 0] = r0[0] + r0[1] + r0[2] + r0[3];
        g_y[z][t * 2 + 1] = r1[0] + r1[1] + r1[2] + r1[3];
    }
}

// ---------------- fused softmax + weighted [.,2] reduction per row ----------------
__global__ __launch_bounds__(256) void softmax_kernel() {
    const int t = blockIdx.x, z = blockIdx.y;
    const float* L = g_align + (size_t)z * 2048 * 2048 + (size_t)t * 2048;
    const float* yv = g_y[z + 1];  // z=0 -> y2 (src values), z=1 -> y3 (tgt values)
    __shared__ float red[3][8];
    const int tid = threadIdx.x, w = tid >> 5, lane = tid & 31;

    float lv[8];
    float m = -1e30f;
#pragma unroll
    for (int i = 0; i < 8; i++) { lv[i] = L[tid + 256 * i]; m = fmaxf(m, lv[i]); }
#pragma unroll
    for (int o = 16; o > 0; o >>= 1) m = fmaxf(m, __shfl_xor_sync(0xffffffffu, m, o));
    if (lane == 0) red[0][w] = m;
    __syncthreads();
    m = fmaxf(fmaxf(fmaxf(red[0][0], red[0][1]), fmaxf(red[0][2], red[0][3])),
              fmaxf(fmaxf(red[0][4], red[0][5]), fmaxf(red[0][6], red[0][7])));
    __syncthreads();

    float Zs = 0.f, w0 = 0.f, w1 = 0.f;
#pragma unroll
    for (int i = 0; i < 8; i++) {
        int s = tid + 256 * i;
        float e = expf(lv[i] - m);
        Zs += e;
        w0 = fmaf(e, yv[s * 2 + 0], w0);
        w1 = fmaf(e, yv[s * 2 + 1], w1);
    }
#pragma unroll
    for (int o = 16; o > 0; o >>= 1) {
        Zs += __shfl_down_sync(0xffffffffu, Zs, o);
        w0 += __shfl_down_sync(0xffffffffu, w0, o);
        w1 += __shfl_down_sync(0xffffffffu, w1, o);
    }
    if (lane == 0) { red[0][w] = Zs; red[1][w] = w0; red[2][w] = w1; }
    __syncthreads();
    if (tid == 0) {
        float Z = 0.f, W0 = 0.f, W1 = 0.f;
#pragma unroll
        for (int q = 0; q < 8; q++) { Z += red[0][q]; W0 += red[1][q]; W1 += red[2][q]; }
        g_ctxE[z][t * 2 + 0] = W0 / Z;
        g_ctxE[z][t * 2 + 1] = W1 / Z;
    }
}

// ---------------- CRF: gold score + partition via parallel log-semiring scan ----------------
__global__ __launch_bounds__(1024) void crf_kernel(
    const int* __restrict__ labels, const float* __restrict__ b_emit,
    const float* __restrict__ t_start, const float* __restrict__ t_trans,
    const float* __restrict__ t_end, float* __restrict__ outp)
{
    const int tid = threadIdx.x;
    __shared__ double red[1024];
    __shared__ float tr[4];
    if (tid < 4) tr[tid] = t_trans[tid];
    __syncthreads();
    const float be0 = b_emit[0], be1 = b_emit[1];

    double acc = 0.0;
    for (int t = tid; t < 2048; t += 1024) {
        float e0 = g_y[0][t * 2 + 0] + g_ctxE[0][t * 2 + 0] + g_ctxE[1][t * 2 + 0] + be0;
        float e1 = g_y[0][t * 2 + 1] + g_ctxE[0][t * 2 + 1] + g_ctxE[1][t * 2 + 1] + be1;
        g_emit[t * 2 + 0] = e0;
        g_emit[t * 2 + 1] = e1;
        int lab = labels[t];
        acc += (double)(lab ? e1 : e0);
        if (t >= 1) {
            acc += (double)tr[lab * 2 + labels[t - 1]];
            // M_t[i][j] = trans[i][j] + emit[t][i], stored at index t-1
            double* M = g_matsA + (size_t)(t - 1) * 4;
            M[0] = (double)tr[0] + (double)e0;
            M[1] = (double)tr[1] + (double)e0;
            M[2] = (double)tr[2] + (double)e1;
            M[3] = (double)tr[3] + (double)e1;
        }
    }
    red[tid] = acc;
    __syncthreads();
    for (int o = 512; o > 0; o >>= 1) {
        if (tid < o) red[tid] += red[tid + o];
        __syncthreads();
    }

    // tree-reduce 2047 matrices: out[i] = arr[2i+1] (later) (x) arr[2i] (earlier)
    double* A = g_matsA;
    double* B = g_matsB;
    int n = 2047;
    while (n > 1) {
        int m = n >> 1;
        for (int i = tid; i < m; i += 1024) {
            const double* Lm = A + (size_t)(2 * i + 1) * 4;
            const double* Rm = A + (size_t)(2 * i) * 4;
            double o0 = lse2d(Lm[0] + Rm[0], Lm[1] + Rm[2]);
            double o1 = lse2d(Lm[0] + Rm[1], Lm[1] + Rm[3]);
            double o2 = lse2d(Lm[2] + Rm[0], Lm[3] + Rm[2]);
            double o3 = lse2d(Lm[2] + Rm[1], Lm[3] + Rm[3]);
            double* O = B + (size_t)i * 4;
            O[0] = o0; O[1] = o1; O[2] = o2; O[3] = o3;
        }
        if ((n & 1) && tid == 0) {
#pragma unroll
            for (int q = 0; q < 4; q++) B[(size_t)m * 4 + q] = A[(size_t)(n - 1) * 4 + q];
        }
        n = m + (n & 1);
        __syncthreads();
        double* tp = A; A = B; B = tp;
    }

    if (tid == 0) {
        double gold = red[0] + (double)t_start[labels[0]] + (double)t_end[labels[2047]];
        double a0 = (double)t_start[0] + (double)g_emit[0];
        double a1 = (double)t_start[1] + (double)g_emit[1];
        const double* Pm = A;
        double aT0 = lse2d(Pm[0] + a0, Pm[1] + a1);
        double aT1 = lse2d(Pm[2] + a0, Pm[3] + a1);
        double logZ = lse2d((double)t_end[0] + aT0, (double)t_end[1] + aT1);
        outp[0] = (float)(gold - logZ);
    }
}

// ---------------- launch ----------------
extern "C" void kernel_launch(void* const* d_in, const int* in_sizes, int n_in,
                              void* d_out, int out_size) {
    const float* source  = (const float*)d_in[0];
    const float* target  = (const float*)d_in[1];
    const int*   labels  = (const int*)d_in[2];
    P4 xs, wih, whh, bih, bhh;
    for (int d = 0; d < 4; d++) {
        int base = 3 + 4 * d;
        wih.p[d] = (const float*)d_in[base + 0];
        whh.p[d] = (const float*)d_in[base + 1];
        bih.p[d] = (const float*)d_in[base + 2];
        bhh.p[d] = (const float*)d_in[base + 3];
        xs.p[d]  = (d < 2) ? source : target;
    }
    const float* W_emit  = (const float*)d_in[19];
    const float* b_emit  = (const float*)d_in[20];
    const float* t_start = (const float*)d_in[21];
    const float* t_trans = (const float*)d_in[22];
    const float* t_end   = (const float*)d_in[23];
    float* outp = (float*)d_out;

    zero_kernel<<<4096, 1024>>>();
    gx_gemm_kernel<<<dim3(12, 16, 4), 256>>>(xs, wih, bih);
    gru_kernel<<<128, 512>>>(whh, bhh);
    logits_gemm_kernel<<<dim3(16, 16, 2), 256>>>();
    y_kernel<<<dim3(2048, 3), 128>>>(W_emit);
    softmax_kernel<<<dim3(2048, 2), 256>>>();
    crf_kernel<<<1, 1024>>>(labels, b_emit, t_start, t_trans, t_end, outp);
}